// round 11
// baseline (speedup 1.0000x reference)
#include <cuda_runtime.h>

#define NB 16
#define G 55                      // blocks per batch (55*16 = 880 <= 148*6)
#define NBLK (G * NB)
#define HWPIX (768*768)
#define NUM_IDS 128
#define NVEC (HWPIX/4)            // 147456
#define FXS 512.0f
#define FXI (1.0f/512.0f)
#define M21 ((1u << 21) - 1)

// ---- scratch (allocation-free __device__ globals). Plain stores fully
// overwritten each run; tickets self-reset. ----
__device__ int   g_pcnt[NBLK * NUM_IDS];
__device__ float g_psin[NBLK * NUM_IDS];
__device__ float g_pcos[NBLK * NUM_IDS];
__device__ int   g_cnt [NB * NUM_IDS];
__device__ float g_fsin[NB * NUM_IDS];
__device__ float g_fcos[NB * NUM_IDS];
__device__ int   g_ni  [NB];
__device__ int   g_nbg [NB];
__device__ int   g_tixb[NB];              // per-batch tickets
__device__ int   g_tixg;                  // global ticket

// ---------------------------------------------------------------------------
// Fused single pass: reads every input byte exactly once.
// Per pixel: TWO u32 atomics into per-WARP shared tables:
//   table A: fx_sin sum in bits[0:21), pixel count in bits[21:32)
//   table B: fx_cos sum
// FXS=512 fixed point; per-warp-bin worst sums ~2e5 << 2^21, count << 2^11.
// Tails (ticketed, overlap with retiring blocks): per-batch partial reduce,
// then global dot + 80-float output.
// ---------------------------------------------------------------------------
__global__ void __launch_bounds__(256, 6)
k_main(const float* __restrict__ pred,
       const int*   __restrict__ inst,
       const float* __restrict__ gt,
       float*       __restrict__ out) {
    const int tid  = threadIdx.x;
    const int warp = tid >> 5;
    const int lane = tid & 31;
    const int b    = blockIdx.y;
    const int bx   = blockIdx.x;

    __shared__ unsigned s_a[8][NUM_IDS];   // sin|count
    __shared__ unsigned s_b[8][NUM_IDS];   // cos
    #pragma unroll
    for (int w = 0; w < 4; w++) {
        s_a[warp][lane + 32 * w] = 0u;
        s_b[warp][lane + 32 * w] = 0u;
    }
    __syncthreads();

    unsigned* ta = s_a[warp];
    unsigned* tb = s_b[warp];
    const int4*   pi = (const int4*)(inst + (size_t)b * HWPIX);
    const float4* ps = (const float4*)(pred + (size_t)b * 2 * HWPIX);
    const float4* pc = (const float4*)(pred + (size_t)b * 2 * HWPIX + HWPIX);
    const float4* gs = (const float4*)(gt + (size_t)b * 5 * HWPIX + 2 * (size_t)HWPIX);
    const float4* gc = (const float4*)(gt + (size_t)b * 5 * HWPIX + 3 * (size_t)HWPIX);

    for (int i = bx * 256 + tid; i < NVEC; i += G * 256) {
        int4   id = __ldcs(pi + i);
        float4 s  = __ldcs(ps + i);
        float4 c  = __ldcs(pc + i);
        float4 g1 = __ldcs(gs + i);
        float4 g2 = __ldcs(gc + i);

        unsigned a0 = __float2uint_rn(fabsf(s.x - g1.x) * FXS) | (1u << 21);
        unsigned a1 = __float2uint_rn(fabsf(s.y - g1.y) * FXS) | (1u << 21);
        unsigned a2 = __float2uint_rn(fabsf(s.z - g1.z) * FXS) | (1u << 21);
        unsigned a3 = __float2uint_rn(fabsf(s.w - g1.w) * FXS) | (1u << 21);
        unsigned b0 = __float2uint_rn(fabsf(c.x - g2.x) * FXS);
        unsigned b1 = __float2uint_rn(fabsf(c.y - g2.y) * FXS);
        unsigned b2 = __float2uint_rn(fabsf(c.z - g2.z) * FXS);
        unsigned b3 = __float2uint_rn(fabsf(c.w - g2.w) * FXS);

        atomicAdd(&ta[id.x], a0);
        atomicAdd(&tb[id.x], b0);
        atomicAdd(&ta[id.y], a1);
        atomicAdd(&tb[id.y], b1);
        atomicAdd(&ta[id.z], a2);
        atomicAdd(&tb[id.z], b2);
        atomicAdd(&ta[id.w], a3);
        atomicAdd(&tb[id.w], b3);
    }
    __syncthreads();

    // flush: combine 8 warp tables -> per-block partials (plain stores)
    if (tid < NUM_IDS) {
        unsigned sn = 0, cn = 0, cs = 0;
        #pragma unroll
        for (int w = 0; w < 8; w++) {
            unsigned va = s_a[w][tid];
            sn += va & M21;
            cn += va >> 21;
            cs += s_b[w][tid];
        }
        const int idx = (b * G + bx) * NUM_IDS + tid;
        g_pcnt[idx] = (int)cn;
        g_psin[idx] = (float)sn * FXI;
        g_pcos[idx] = (float)cs * FXI;
    }

    // ---- per-batch ticket tail: reduce this batch's G partials ------------
    __shared__ int s_lastb;
    if (tid == 0) {
        __threadfence();
        s_lastb = (atomicAdd(&g_tixb[b], 1) == G - 1);
    }
    __syncthreads();
    if (!s_lastb) return;
    __threadfence();

    {
        const int id = tid & 127;
        const int j  = tid >> 7;          // 0..1
        int   cn = 0;
        float fs = 0.0f, fc = 0.0f;
        #pragma unroll
        for (int x = j; x < G; x += 2) {
            const int idx = (b * G + x) * NUM_IDS + id;
            cn += g_pcnt[idx];
            fs += g_psin[idx];
            fc += g_pcos[idx];
        }
        __shared__ int   spc[2][NUM_IDS];
        __shared__ float sps[2][NUM_IDS];
        __shared__ float spq[2][NUM_IDS];
        spc[j][id] = cn; sps[j][id] = fs; spq[j][id] = fc;
        __syncthreads();

        __shared__ int s_wni[4];
        if (j == 0) {                      // tid 0..127, warps 0..3
            cn += spc[1][id];
            g_cnt [b * NUM_IDS + id] = cn;
            g_fsin[b * NUM_IDS + id] = fs + sps[1][id];
            g_fcos[b * NUM_IDS + id] = fc + spq[1][id];
            unsigned ball = __ballot_sync(0xFFFFFFFFu, id > 0 && cn > 0);
            if (lane == 0) s_wni[warp] = __popc(ball);
            if (id == 0) g_nbg[b] = cn;
        }
        __syncthreads();
        if (tid == 0) {
            g_ni[b]   = s_wni[0] + s_wni[1] + s_wni[2] + s_wni[3];
            g_tixb[b] = 0;                 // self-reset
        }
    }

    // ---- global ticket tail: weights dot + 80-float output ----------------
    __shared__ int s_lastg;
    if (tid == 0) {
        __threadfence();
        s_lastg = (atomicAdd(&g_tixg, 1) == NB - 1);
    }
    __syncthreads();
    if (!s_lastg) return;
    __threadfence();

    int ni = 0, nbg = 0;
    #pragma unroll
    for (int i = 0; i < NB; i++) { ni += g_ni[i]; nbg += g_nbg[i]; }
    const float inv_bg = 1.0f / (2.0f * (float)nbg);
    const float two_ni = 2.0f * (float)ni;

    for (int bb = warp; bb < NB; bb += 8) {       // warp w -> batches w, w+8
        float asin_ = 0.0f, acos_ = 0.0f;
        #pragma unroll
        for (int l = lane; l < NUM_IDS; l += 32) {
            const int idx = bb * NUM_IDS + l;
            int   c   = g_cnt[idx];
            float inv = (l == 0) ? inv_bg
                                 : ((c > 0) ? 1.0f / ((float)c * two_ni) : 0.0f);
            asin_ += g_fsin[idx] * inv;
            acos_ += g_fcos[idx] * inv;
        }
        for (int off = 16; off > 0; off >>= 1) {
            asin_ += __shfl_down_sync(0xFFFFFFFFu, asin_, off);
            acos_ += __shfl_down_sync(0xFFFFFFFFu, acos_, off);
        }
        if (lane == 0) {
            float t = asin_ + acos_;
            out[0 * NB + bb] = t;       // loss
            out[1 * NB + bb] = t;       // loss_direction_total
            out[2 * NB + bb] = 0.0f;    // loss_centers
            out[3 * NB + bb] = asin_;   // loss_sin
            out[4 * NB + bb] = acos_;   // loss_cos
        }
    }
    if (tid == 0) g_tixg = 0;            // self-reset
}

extern "C" void kernel_launch(void* const* d_in, const int* in_sizes, int n_in,
                              void* d_out, int out_size) {
    const float* pred = (const float*)d_in[0];   // (16,2,768,768) f32
    const int*   inst = (const int*)d_in[1];     // (16,768,768) i32
    // d_in[2] = labels (unused: W_FG == W_BG == 1)
    const float* gt   = (const float*)d_in[3];   // (16,5,768,768) f32
    float* out = (float*)d_out;                  // 80 f32

    k_main<<<dim3(G, NB), 256>>>(pred, inst, gt, out);
}